// round 3
// baseline (speedup 1.0000x reference)
#include <cuda_runtime.h>

#define NN 8192
#define DD 512
#define NCLS_MAX 256
#define LOG2E 1.4426950408889634f

// ---------------- scratch (static device arrays; no allocation) ----------------
__device__ float g_rowsum[NN];     // sum_j exp(sim_ij)  (all j, incl self)
__device__ float g_pos_sum[NN];    // sum_{same, s<1} exp(1-s)
__device__ float g_same_exp[NN];   // sum_{same} exp(s)  (incl self)
__device__ float g_colsum[DD];     // sum_i x_i  (for last-row neg mean)
__device__ int   g_cls_cnt[NCLS_MAX];
__device__ int   g_cls_off[NCLS_MAX];
__device__ int   g_cls_fill[NCLS_MAX];
__device__ int   g_members[NN];    // CSR member lists by class
__device__ float g_last_possim;
__device__ int   g_last_poscnt;
__device__ float g_last_samesim;

__device__ __forceinline__ float fexp2(float x) {
    float y; asm("ex2.approx.ftz.f32 %0, %1;" : "=f"(y) : "f"(x)); return y;
}

__device__ __forceinline__ int cls_of(const int* __restrict__ T, int i) {
    int c = T[i];
    c = c < 0 ? 0 : (c >= NCLS_MAX ? NCLS_MAX - 1 : c);
    return c;
}

#define PACK2(d, x, y)   asm("mov.b64 %0, {%1, %2};" : "=l"(d) : "f"(x), "f"(y))
#define UNPACK2(x, y, d) asm("mov.b64 {%0, %1}, %2;" : "=f"(x), "=f"(y) : "l"(d))
#define FMA2(d, a, b, c) asm("fma.rn.f32x2 %0, %1, %2, %3;" : "=l"(d) : "l"(a), "l"(b), "l"(c))

// ---------------- 0: zero scratch ----------------
__global__ void k_zero() {
    int idx = blockIdx.x * blockDim.x + threadIdx.x;
    if (idx < NN) g_rowsum[idx] = 0.f;
    if (idx < DD) g_colsum[idx] = 0.f;
    if (idx < NCLS_MAX) { g_cls_cnt[idx] = 0; g_cls_fill[idx] = 0; }
    if (idx == 0) { g_last_possim = 0.f; g_last_poscnt = 0; g_last_samesim = 0.f; }
}

// ---------------- 1: class histogram ----------------
__global__ void k_count(const int* __restrict__ T) {
    int idx = blockIdx.x * blockDim.x + threadIdx.x;
    if (idx < NN) atomicAdd(&g_cls_cnt[cls_of(T, idx)], 1);
}

// ---------------- 2: prefix offsets (serial, tiny) ----------------
__global__ void k_offsets() {
    if (threadIdx.x == 0 && blockIdx.x == 0) {
        int s = 0;
        for (int c = 0; c < NCLS_MAX; ++c) { g_cls_off[c] = s; s += g_cls_cnt[c]; }
    }
}

// ---------------- 3: scatter members (CSR) ----------------
__global__ void k_scatter(const int* __restrict__ T) {
    int idx = blockIdx.x * blockDim.x + threadIdx.x;
    if (idx < NN) {
        int c = cls_of(T, idx);
        int p = atomicAdd(&g_cls_fill[c], 1);
        g_members[g_cls_off[c] + p] = idx;
    }
}

// ---------------- 4: column sums of X ----------------
__global__ void k_colsum(const float* __restrict__ X) {
    int d = threadIdx.x;                  // 512 threads
    int r0 = blockIdx.x * 128;            // 64 blocks
    float acc = 0.f;
    for (int r = r0; r < r0 + 128; ++r) acc += X[(size_t)r * DD + d];
    atomicAdd(&g_colsum[d], acc);
}

// ---------------- 5: same-class pairs (accurate path) ----------------
__global__ void k_same(const float* __restrict__ X, const int* __restrict__ T) {
    int i = blockIdx.x;
    int tid = threadIdx.x, lane = tid & 31, w = tid >> 5;  // 128 threads, 4 warps
    __shared__ float xi[DD];
    __shared__ float r_se[4], r_pos[4], r_ps[4], r_ss[4];
    __shared__ int   r_pc[4];
    int c = cls_of(T, i);
    for (int d = tid; d < DD; d += 128) xi[d] = X[(size_t)i * DD + d];
    __syncthreads();

    int off = g_cls_off[c], cnt = g_cls_cnt[c];
    float a_se = 0.f, a_pos = 0.f, a_ps = 0.f, a_ss = 0.f;
    int   a_pc = 0;

    for (int m = w; m < cnt; m += 4) {
        int j = g_members[off + m];
        float s;
        bool lt1;
        if (j == i) {
            // diagonal: fp64 so the (sim_ii < 1) decision is as close to truth as possible
            double sd = 0.0;
            for (int d = lane; d < DD; d += 32) {
                double v = (double)xi[d];
                sd += v * v;
            }
            #pragma unroll
            for (int o = 16; o; o >>= 1) sd += __shfl_xor_sync(0xffffffffu, sd, o);
            s = (float)sd;
            lt1 = (sd < 1.0);
        } else {
            const float* xj = X + (size_t)j * DD;
            float sf = 0.f;
            for (int d = lane; d < DD; d += 32) sf += xi[d] * xj[d];
            #pragma unroll
            for (int o = 16; o; o >>= 1) sf += __shfl_xor_sync(0xffffffffu, sf, o);
            s = sf;
            lt1 = (s < 1.0f);
        }
        if (lane == 0) {
            float e = expf(s);
            a_se += e;
            a_ss += s;
            if (lt1) { a_pos += expf(1.0f - s); a_ps += s; a_pc += 1; }
        }
    }
    if (lane == 0) { r_se[w] = a_se; r_pos[w] = a_pos; r_ps[w] = a_ps; r_ss[w] = a_ss; r_pc[w] = a_pc; }
    __syncthreads();
    if (tid == 0) {
        float se = 0.f, po = 0.f, ps = 0.f, ss = 0.f; int pc = 0;
        #pragma unroll
        for (int k = 0; k < 4; ++k) { se += r_se[k]; po += r_pos[k]; ps += r_ps[k]; ss += r_ss[k]; pc += r_pc[k]; }
        g_same_exp[i] = se;
        g_pos_sum[i]  = po;
        if (i == NN - 1) { g_last_possim = ps; g_last_poscnt = pc; g_last_samesim = ss; }
    }
}

// ---------------- 6: main fused GEMM row-sum of exp(sim) ----------------
#define BM 128
#define BN 128
#define BK 16
#define NSPLIT 4
#define COLS_PER (NN / NSPLIT)

__global__ void __launch_bounds__(256, 2) k_rowsum(const float* __restrict__ X) {
    __shared__ float sA[BK][BM];
    __shared__ float sB[BK][BN];
    __shared__ float srow[BM];

    int tid = threadIdx.x;
    int tx = tid & 15, ty = tid >> 4;
    int rowBase = blockIdx.x * BM;
    int colBase0 = blockIdx.y * COLS_PER;

    float rowexp[8];
    #pragma unroll
    for (int r = 0; r < 8; ++r) rowexp[r] = 0.f;

    for (int jt = 0; jt < COLS_PER / BN; ++jt) {
        int colBase = colBase0 + jt * BN;
        unsigned long long acc[8][4];
        #pragma unroll
        for (int r = 0; r < 8; ++r)
            #pragma unroll
            for (int cc = 0; cc < 4; ++cc) acc[r][cc] = 0ull;

        for (int kt = 0; kt < DD / BK; ++kt) {
            #pragma unroll
            for (int l = 0; l < 2; ++l) {
                int f = tid + l * 256;          // 0..511
                int r = f >> 2;
                int k4 = (f & 3) * 4;
                float4 va = *(const float4*)&X[(size_t)(rowBase + r) * DD + kt * BK + k4];
                sA[k4 + 0][r] = va.x; sA[k4 + 1][r] = va.y; sA[k4 + 2][r] = va.z; sA[k4 + 3][r] = va.w;
                float4 vb = *(const float4*)&X[(size_t)(colBase + r) * DD + kt * BK + k4];
                sB[k4 + 0][r] = vb.x; sB[k4 + 1][r] = vb.y; sB[k4 + 2][r] = vb.z; sB[k4 + 3][r] = vb.w;
            }
            __syncthreads();
            #pragma unroll
            for (int k = 0; k < BK; ++k) {
                float4 a0 = *(const float4*)&sA[k][ty * 8];
                float4 a1 = *(const float4*)&sA[k][ty * 8 + 4];
                const unsigned long long* pb = (const unsigned long long*)&sB[k][tx * 8];
                unsigned long long b0 = pb[0], b1 = pb[1], b2 = pb[2], b3 = pb[3];
                float av[8] = {a0.x, a0.y, a0.z, a0.w, a1.x, a1.y, a1.z, a1.w};
                #pragma unroll
                for (int r = 0; r < 8; ++r) {
                    unsigned long long ad;
                    PACK2(ad, av[r], av[r]);
                    FMA2(acc[r][0], ad, b0, acc[r][0]);
                    FMA2(acc[r][1], ad, b1, acc[r][1]);
                    FMA2(acc[r][2], ad, b2, acc[r][2]);
                    FMA2(acc[r][3], ad, b3, acc[r][3]);
                }
            }
            __syncthreads();
        }
        // epilogue: exp and accumulate into per-row partials
        #pragma unroll
        for (int r = 0; r < 8; ++r) {
            float se = 0.f;
            #pragma unroll
            for (int cc = 0; cc < 4; ++cc) {
                float lo, hi;
                UNPACK2(lo, hi, acc[r][cc]);
                se += fexp2(lo * LOG2E);
                se += fexp2(hi * LOG2E);
            }
            rowexp[r] += se;
        }
    }

    if (tid < BM) srow[tid] = 0.f;
    __syncthreads();
    #pragma unroll
    for (int r = 0; r < 8; ++r) atomicAdd(&srow[ty * 8 + r], rowexp[r]);
    __syncthreads();
    if (tid < BM) atomicAdd(&g_rowsum[rowBase + tid], srow[tid]);
}

// ---------------- 7: final reduction ----------------
__global__ void k_final(const float* __restrict__ X, const int* __restrict__ T,
                        float* __restrict__ out, int out_n) {
    __shared__ float sred[256];
    __shared__ int   sskip[256];
    int tid = threadIdx.x;

    // last-row total sim = x_last . colsum
    float lt = 0.f;
    for (int d = tid; d < DD; d += 256) lt += X[(size_t)(NN - 1) * DD + d] * g_colsum[d];
    sred[tid] = lt;
    __syncthreads();
    for (int o = 128; o; o >>= 1) { if (tid < o) sred[tid] += sred[tid + o]; __syncthreads(); }
    float last_total = sred[0];
    __syncthreads();

    float lsum = 0.f; int skip = 0;
    for (int i = tid; i < NN; i += 256) {
        int cnt = g_cls_cnt[cls_of(T, i)];
        if (cnt < NN) {
            float neg = g_rowsum[i] - g_same_exp[i];
            lsum += logf(g_pos_sum[i]) + logf(neg);
        } else {
            skip += 1;
        }
    }
    sred[tid] = lsum; sskip[tid] = skip;
    __syncthreads();
    for (int o = 128; o; o >>= 1) {
        if (tid < o) { sred[tid] += sred[tid + o]; sskip[tid] += sskip[tid + o]; }
        __syncthreads();
    }
    if (tid == 0) {
        float loss = sred[0] / (float)NN;
        float prec = (float)sskip[0] / (float)NN;
        int clast = g_cls_cnt[cls_of(T, NN - 1)];
        float mean_pos = g_last_possim / (float)g_last_poscnt;
        float mean_neg = (last_total - g_last_samesim) / (float)(NN - clast);
        if (out_n > 0) out[0] = loss;
        if (out_n > 1) out[1] = prec;
        if (out_n > 2) out[2] = mean_pos;
        if (out_n > 3) out[3] = mean_neg;
    }
}

// ---------------- launch ----------------
extern "C" void kernel_launch(void* const* d_in, const int* in_sizes, int n_in,
                              void* d_out, int out_size) {
    const float* X = (const float*)d_in[0];
    const int*   T = (const int*)d_in[1];
    float* out = (float*)d_out;

    k_zero<<<32, 256>>>();
    k_count<<<32, 256>>>(T);
    k_offsets<<<1, 32>>>();
    k_scatter<<<32, 256>>>(T);
    k_colsum<<<64, 512>>>(X);
    k_same<<<NN, 128>>>(X, T);
    dim3 grid(NN / BM, NSPLIT);
    k_rowsum<<<grid, 256>>>(X);
    k_final<<<1, 256>>>(X, T, out, out_size);
}

// round 5
// speedup vs baseline: 5.5465x; 5.5465x over previous
#include <cuda_runtime.h>
#include <cuda_bf16.h>
#include <cstdint>

#define NN 8192
#define DD 512
#define NCLS_MAX 256
#define LOG2E 1.4426950408889634f

// ---------------- scratch (static device arrays; no allocation) ----------------
__device__ float g_rowsum[NN];     // sum_j exp(sim_ij)  (all j, incl self)
__device__ float g_pos_sum[NN];    // sum_{same, s<1} exp(1-s)
__device__ float g_same_exp[NN];   // sum_{same} exp(s)  (incl self)
__device__ float g_colsum[DD];     // sum_i x_i
__device__ int   g_cls_cnt[NCLS_MAX];
__device__ int   g_cls_off[NCLS_MAX];
__device__ int   g_cls_fill[NCLS_MAX];
__device__ int   g_members[NN];
__device__ float g_last_possim;
__device__ int   g_last_poscnt;
__device__ float g_last_samesim;
__device__ __nv_bfloat16 g_xbf[NN * DD];   // bf16 copy of X (8 MB)

__device__ __forceinline__ float fexp2(float x) {
    float y; asm("ex2.approx.ftz.f32 %0, %1;" : "=f"(y) : "f"(x)); return y;
}

__device__ __forceinline__ int cls_of(const int* __restrict__ T, int i) {
    int c = T[i];
    c = c < 0 ? 0 : (c >= NCLS_MAX ? NCLS_MAX - 1 : c);
    return c;
}

__device__ __forceinline__ uint32_t smem_u32(const void* p) {
    uint32_t a;
    asm("{ .reg .u64 t; cvta.to.shared.u64 t, %1; cvt.u32.u64 %0, t; }" : "=r"(a) : "l"(p));
    return a;
}

__device__ __forceinline__ void cpa16(uint32_t s, const void* g) {
    asm volatile("cp.async.cg.shared.global [%0], [%1], 16;" :: "r"(s), "l"(g));
}
#define CP_COMMIT() asm volatile("cp.async.commit_group;" ::: "memory")

__device__ __forceinline__ void ldsm_x4(uint32_t& r0, uint32_t& r1, uint32_t& r2, uint32_t& r3,
                                        uint32_t addr) {
    asm volatile("ldmatrix.sync.aligned.m8n8.x4.shared.b16 {%0,%1,%2,%3}, [%4];"
                 : "=r"(r0), "=r"(r1), "=r"(r2), "=r"(r3) : "r"(addr));
}

__device__ __forceinline__ void mma16816(float* c, uint32_t a0, uint32_t a1, uint32_t a2,
                                         uint32_t a3, uint32_t b0, uint32_t b1) {
    asm volatile("mma.sync.aligned.m16n8k16.row.col.f32.bf16.bf16.f32 "
                 "{%0,%1,%2,%3}, {%4,%5,%6,%7}, {%8,%9}, {%0,%1,%2,%3};"
                 : "+f"(c[0]), "+f"(c[1]), "+f"(c[2]), "+f"(c[3])
                 : "r"(a0), "r"(a1), "r"(a2), "r"(a3), "r"(b0), "r"(b1));
}

// ---------------- small setup kernels ----------------
__global__ void k_tobf16(const float* __restrict__ X) {
    int t = blockIdx.x * blockDim.x + threadIdx.x;
    size_t base = (size_t)t * 8;
    float4 a = *(const float4*)&X[base];
    float4 b = *(const float4*)&X[base + 4];
    __nv_bfloat162 o[4];
    o[0] = __floats2bfloat162_rn(a.x, a.y);
    o[1] = __floats2bfloat162_rn(a.z, a.w);
    o[2] = __floats2bfloat162_rn(b.x, b.y);
    o[3] = __floats2bfloat162_rn(b.z, b.w);
    *(uint4*)&g_xbf[base] = *(const uint4*)o;
}

__global__ void k_zero() {
    int idx = blockIdx.x * blockDim.x + threadIdx.x;
    if (idx < NN) g_rowsum[idx] = 0.f;
    if (idx < DD) g_colsum[idx] = 0.f;
    if (idx < NCLS_MAX) { g_cls_cnt[idx] = 0; g_cls_fill[idx] = 0; }
    if (idx == 0) { g_last_possim = 0.f; g_last_poscnt = 0; g_last_samesim = 0.f; }
}

__global__ void k_count(const int* __restrict__ T) {
    int idx = blockIdx.x * blockDim.x + threadIdx.x;
    if (idx < NN) atomicAdd(&g_cls_cnt[cls_of(T, idx)], 1);
}

__global__ void k_offsets() {
    if (threadIdx.x == 0 && blockIdx.x == 0) {
        int s = 0;
        for (int c = 0; c < NCLS_MAX; ++c) { g_cls_off[c] = s; s += g_cls_cnt[c]; }
    }
}

__global__ void k_scatter(const int* __restrict__ T) {
    int idx = blockIdx.x * blockDim.x + threadIdx.x;
    if (idx < NN) {
        int c = cls_of(T, idx);
        int p = atomicAdd(&g_cls_fill[c], 1);
        g_members[g_cls_off[c] + p] = idx;
    }
}

// ---------------- main: bf16 mma.sync Gram row-sum of exp(sim) ----------------
// CTA tile 128x128, BK=64, 2-stage cp.async. 8 warps, warp tile 32x64.
// SMEM row stride 72 bf16 (144 B) -> ldmatrix bank-conflict-free.
#define BK 64
#define KSTEPS (DD / BK)           // 8
#define ROWSTRIDE 144              // bytes per smem row (72 bf16)
#define BUFB (128 * ROWSTRIDE)     // 18432 B per matrix buffer
#define SM_DYN (4 * BUFB)          // A0,B0,A1,B1 = 73728 B

__global__ void __launch_bounds__(256) k_rowsum_mma() {
    extern __shared__ char smem[];
    __shared__ float srow[128];
    uint32_t sb = smem_u32(smem);
    int tid = threadIdx.x, lane = tid & 31, wid = tid >> 5;
    int wm = wid & 3, wn = wid >> 2;          // warp tile: rows wm*32..+31, cols wn*64..+63
    int rowBase = blockIdx.x * 128;
    int colBase = blockIdx.y * 128;

    if (tid < 128) srow[tid] = 0.f;

    float acc[2][8][4];
    #pragma unroll
    for (int mb = 0; mb < 2; ++mb)
        #pragma unroll
        for (int j = 0; j < 8; ++j)
            #pragma unroll
            for (int q = 0; q < 4; ++q) acc[mb][j][q] = 0.f;

    // per-thread load coords (1024 segs of 16B per matrix, 4 per thread)
    int lrow[4], lseg[4];
    #pragma unroll
    for (int it = 0; it < 4; ++it) {
        int idx = it * 256 + tid;
        lrow[it] = idx >> 3;
        lseg[it] = idx & 7;
    }

    // prologue: stage 0
    {
        uint32_t aB = sb, bB = sb + BUFB;
        #pragma unroll
        for (int it = 0; it < 4; ++it) {
            uint32_t so = (uint32_t)(lrow[it] * ROWSTRIDE + lseg[it] * 16);
            cpa16(aB + so, &g_xbf[(size_t)(rowBase + lrow[it]) * DD + lseg[it] * 8]);
            cpa16(bB + so, &g_xbf[(size_t)(colBase + lrow[it]) * DD + lseg[it] * 8]);
        }
        CP_COMMIT();
    }

    // lane-invariant fragment address offsets
    int aRow = (lane & 15);                       // + wm*32 + mb*16
    int aK8  = (lane >> 4) << 3;
    int bN   = (lane & 7) + ((lane >> 4) << 3);   // + wn*64 + nb*16
    int bK8  = ((lane >> 3) & 1) << 3;

    for (int kt = 0; kt < KSTEPS; ++kt) {
        int cur = kt & 1;
        if (kt < KSTEPS - 1) {
            int nxt = (kt + 1) & 1;
            uint32_t aB = sb + nxt * 2 * BUFB, bB = aB + BUFB;
            int kOff = (kt + 1) * BK;
            #pragma unroll
            for (int it = 0; it < 4; ++it) {
                uint32_t so = (uint32_t)(lrow[it] * ROWSTRIDE + lseg[it] * 16);
                cpa16(aB + so, &g_xbf[(size_t)(rowBase + lrow[it]) * DD + kOff + lseg[it] * 8]);
                cpa16(bB + so, &g_xbf[(size_t)(colBase + lrow[it]) * DD + kOff + lseg[it] * 8]);
            }
            CP_COMMIT();
            asm volatile("cp.async.wait_group 1;" ::: "memory");
        } else {
            asm volatile("cp.async.wait_group 0;" ::: "memory");
        }
        __syncthreads();

        uint32_t aBase = sb + cur * 2 * BUFB;
        uint32_t bBase = aBase + BUFB;
        #pragma unroll
        for (int kk = 0; kk < BK / 16; ++kk) {
            int k0 = kk * 16;
            uint32_t a[2][4];
            #pragma unroll
            for (int mb = 0; mb < 2; ++mb) {
                uint32_t addr = aBase + (uint32_t)((wm * 32 + mb * 16 + aRow) * ROWSTRIDE
                                                   + (k0 + aK8) * 2);
                ldsm_x4(a[mb][0], a[mb][1], a[mb][2], a[mb][3], addr);
            }
            #pragma unroll
            for (int nb = 0; nb < 4; ++nb) {
                uint32_t addr = bBase + (uint32_t)((wn * 64 + nb * 16 + bN) * ROWSTRIDE
                                                   + (k0 + bK8) * 2);
                uint32_t b0, b1, b2, b3;
                ldsm_x4(b0, b1, b2, b3, addr);
                #pragma unroll
                for (int mb = 0; mb < 2; ++mb) {
                    mma16816(acc[mb][nb * 2 + 0], a[mb][0], a[mb][1], a[mb][2], a[mb][3], b0, b1);
                    mma16816(acc[mb][nb * 2 + 1], a[mb][0], a[mb][1], a[mb][2], a[mb][3], b2, b3);
                }
            }
        }
        __syncthreads();
    }

    // epilogue: exp + row-sum.  lane holds rows (lane/4) and (lane/4)+8 of each 16-row block
    #pragma unroll
    for (int mb = 0; mb < 2; ++mb) {
        float slo = 0.f, shi = 0.f;
        #pragma unroll
        for (int j = 0; j < 8; ++j) {
            slo += fexp2(acc[mb][j][0] * LOG2E) + fexp2(acc[mb][j][1] * LOG2E);
            shi += fexp2(acc[mb][j][2] * LOG2E) + fexp2(acc[mb][j][3] * LOG2E);
        }
        slo += __shfl_xor_sync(0xffffffffu, slo, 1);
        slo += __shfl_xor_sync(0xffffffffu, slo, 2);
        shi += __shfl_xor_sync(0xffffffffu, shi, 1);
        shi += __shfl_xor_sync(0xffffffffu, shi, 2);
        if ((lane & 3) == 0) {
            int r = wm * 32 + mb * 16 + (lane >> 2);
            atomicAdd(&srow[r], slo);
            atomicAdd(&srow[r + 8], shi);
        }
    }
    __syncthreads();
    if (tid < 128) atomicAdd(&g_rowsum[rowBase + tid], srow[tid]);
}

// ---------------- column sums of X ----------------
__global__ void k_colsum(const float* __restrict__ X) {
    int d = threadIdx.x;
    int r0 = blockIdx.x * 128;
    float acc = 0.f;
    for (int r = r0; r < r0 + 128; ++r) acc += X[(size_t)r * DD + d];
    atomicAdd(&g_colsum[d], acc);
}

// ---------------- same-class pairs (accurate path) ----------------
__global__ void k_same(const float* __restrict__ X, const int* __restrict__ T) {
    int i = blockIdx.x;
    int tid = threadIdx.x, lane = tid & 31, w = tid >> 5;
    __shared__ float xi[DD];
    __shared__ float r_se[4], r_pos[4], r_ps[4], r_ss[4];
    __shared__ int   r_pc[4];
    int c = cls_of(T, i);
    for (int d = tid; d < DD; d += 128) xi[d] = X[(size_t)i * DD + d];
    __syncthreads();

    int off = g_cls_off[c], cnt = g_cls_cnt[c];
    float a_se = 0.f, a_pos = 0.f, a_ps = 0.f, a_ss = 0.f;
    int   a_pc = 0;

    for (int m = w; m < cnt; m += 4) {
        int j = g_members[off + m];
        float s;
        bool lt1;
        if (j == i) {
            double sd = 0.0;
            for (int d = lane; d < DD; d += 32) {
                double v = (double)xi[d];
                sd += v * v;
            }
            #pragma unroll
            for (int o = 16; o; o >>= 1) sd += __shfl_xor_sync(0xffffffffu, sd, o);
            s = (float)sd;
            lt1 = (sd < 1.0);
        } else {
            const float* xj = X + (size_t)j * DD;
            float sf = 0.f;
            for (int d = lane; d < DD; d += 32) sf += xi[d] * xj[d];
            #pragma unroll
            for (int o = 16; o; o >>= 1) sf += __shfl_xor_sync(0xffffffffu, sf, o);
            s = sf;
            lt1 = (s < 1.0f);
        }
        if (lane == 0) {
            float e = expf(s);
            a_se += e;
            a_ss += s;
            if (lt1) { a_pos += expf(1.0f - s); a_ps += s; a_pc += 1; }
        }
    }
    if (lane == 0) { r_se[w] = a_se; r_pos[w] = a_pos; r_ps[w] = a_ps; r_ss[w] = a_ss; r_pc[w] = a_pc; }
    __syncthreads();
    if (tid == 0) {
        float se = 0.f, po = 0.f, ps = 0.f, ss = 0.f; int pc = 0;
        #pragma unroll
        for (int k = 0; k < 4; ++k) { se += r_se[k]; po += r_pos[k]; ps += r_ps[k]; ss += r_ss[k]; pc += r_pc[k]; }
        g_same_exp[i] = se;
        g_pos_sum[i]  = po;
        if (i == NN - 1) { g_last_possim = ps; g_last_poscnt = pc; g_last_samesim = ss; }
    }
}

// ---------------- final reduction ----------------
__global__ void k_final(const float* __restrict__ X, const int* __restrict__ T,
                        float* __restrict__ out, int out_n) {
    __shared__ float sred[256];
    __shared__ int   sskip[256];
    int tid = threadIdx.x;

    float lt = 0.f;
    for (int d = tid; d < DD; d += 256) lt += X[(size_t)(NN - 1) * DD + d] * g_colsum[d];
    sred[tid] = lt;
    __syncthreads();
    for (int o = 128; o; o >>= 1) { if (tid < o) sred[tid] += sred[tid + o]; __syncthreads(); }
    float last_total = sred[0];
    __syncthreads();

    float lsum = 0.f; int skip = 0;
    for (int i = tid; i < NN; i += 256) {
        int cnt = g_cls_cnt[cls_of(T, i)];
        if (cnt < NN) {
            float neg = g_rowsum[i] - g_same_exp[i];
            lsum += logf(g_pos_sum[i]) + logf(neg);
        } else {
            skip += 1;
        }
    }
    sred[tid] = lsum; sskip[tid] = skip;
    __syncthreads();
    for (int o = 128; o; o >>= 1) {
        if (tid < o) { sred[tid] += sred[tid + o]; sskip[tid] += sskip[tid + o]; }
        __syncthreads();
    }
    if (tid == 0) {
        float loss = sred[0] / (float)NN;
        float prec = (float)sskip[0] / (float)NN;
        int clast = g_cls_cnt[cls_of(T, NN - 1)];
        float mean_pos = g_last_possim / (float)g_last_poscnt;
        float mean_neg = (last_total - g_last_samesim) / (float)(NN - clast);
        if (out_n > 0) out[0] = loss;
        if (out_n > 1) out[1] = prec;
        if (out_n > 2) out[2] = mean_pos;
        if (out_n > 3) out[3] = mean_neg;
    }
}

// ---------------- launch ----------------
extern "C" void kernel_launch(void* const* d_in, const int* in_sizes, int n_in,
                              void* d_out, int out_size) {
    const float* X = (const float*)d_in[0];
    const int*   T = (const int*)d_in[1];
    float* out = (float*)d_out;

    static bool attr_set = false;
    if (!attr_set) {
        cudaFuncSetAttribute(k_rowsum_mma, cudaFuncAttributeMaxDynamicSharedMemorySize, SM_DYN);
        attr_set = true;
    }

    // order chosen so ncu (-s 5 -c 1) profiles k_rowsum_mma (launch #6)
    k_tobf16<<<2048, 256>>>(X);               // 1
    k_zero<<<32, 256>>>();                    // 2
    k_count<<<32, 256>>>(T);                  // 3
    k_offsets<<<1, 32>>>();                   // 4
    k_scatter<<<32, 256>>>(T);                // 5
    dim3 grid(NN / 128, NN / 128);
    k_rowsum_mma<<<grid, 256, SM_DYN>>>();    // 6  <-- profiled
    k_colsum<<<64, 512>>>(X);                 // 7
    k_same<<<NN, 128>>>(X, T);                // 8
    k_final<<<1, 256>>>(X, T, out, out_size); // 9
}